// round 2
// baseline (speedup 1.0000x reference)
#include <cuda_runtime.h>
#include <cstddef>

#define N_MEM 8
#define BATCH 64
#define D_K 256
#define D_V 256
#define KCHUNK 64   // k-rows per CTA (D_K / 4)

// out layout: new_states [N_MEM, B, D_K, D_V] followed by readouts [N_MEM, B, D_V]
#define STATES_ELEMS ((size_t)N_MEM * BATCH * D_K * D_V)
#define READ_ELEMS   ((size_t)N_MEM * BATCH * D_V)

__global__ __launch_bounds__(256, 4)
void mom_fused_kernel(const float* __restrict__ states,
                      const float* __restrict__ key,
                      const float* __restrict__ value,
                      const float* __restrict__ alpha,
                      const float* __restrict__ rho,
                      const float* __restrict__ lam,
                      const float* __restrict__ query,
                      float* __restrict__ out_states,
                      float* __restrict__ out_read)
{
    // blockIdx.x = (n*BATCH + b) * 4 + kchunk
    const int blk = blockIdx.x;
    const int nb  = blk >> 2;        // slice index: n*BATCH + b
    const int kc  = blk & 3;         // which 64-row k chunk
    const int n   = nb / BATCH;
    const int b   = nb - n * BATCH;

    const int tx  = threadIdx.x;     // 0..63 : D_V in float4 units
    const int ty  = threadIdx.y;     // 0..3  : k-row partition within chunk
    const int tid = ty * 64 + tx;

    const float lam_s = lam[b * N_MEM + n];
    const float w     = rho[b * N_MEM + n] * alpha[b];

    __shared__ float skey[KCHUNK];
    __shared__ float sq[KCHUNK];
    if (tid < KCHUNK) {
        const int k = kc * KCHUNK + tid;
        skey[tid] = key[b * D_K + k] * w;  // pre-scale key by write strength
        sq[tid]   = query[b * D_K + k];
    }
    __syncthreads();

    const size_t base = (size_t)nb * D_K * D_V + (size_t)kc * KCHUNK * D_V;
    const float4* __restrict__ st  = (const float4*)(states + base);
    float4* __restrict__       ost = (float4*)(out_states + base);

    const float4 val4 = ((const float4*)(value + b * D_V))[tx];

    float4 acc = make_float4(0.f, 0.f, 0.f, 0.f);

    // 16 k-rows per thread, streaming loads/stores (no reuse -> evict-first)
    #pragma unroll 4
    for (int kk = ty; kk < KCHUNK; kk += 4) {
        float4 s = __ldcs(&st[kk * 64 + tx]);
        const float kw = skey[kk];
        float4 ns;
        ns.x = lam_s * s.x + kw * val4.x;
        ns.y = lam_s * s.y + kw * val4.y;
        ns.z = lam_s * s.z + kw * val4.z;
        ns.w = lam_s * s.w + kw * val4.w;
        __stcs(&ost[kk * 64 + tx], ns);
        const float q = sq[kk];
        acc.x += q * ns.x;
        acc.y += q * ns.y;
        acc.z += q * ns.z;
        acc.w += q * ns.w;
    }

    // Cross-ty reduction, then one float4-worth of atomics per lane
    __shared__ float4 red[4][64];
    red[ty][tx] = acc;
    __syncthreads();
    if (ty == 0) {
        float4 r0 = red[0][tx];
        float4 r1 = red[1][tx];
        float4 r2 = red[2][tx];
        float4 r3 = red[3][tx];
        float* dst = out_read + (size_t)nb * D_V + tx * 4;
        atomicAdd(dst + 0, (r0.x + r1.x) + (r2.x + r3.x));
        atomicAdd(dst + 1, (r0.y + r1.y) + (r2.y + r3.y));
        atomicAdd(dst + 2, (r0.z + r1.z) + (r2.z + r3.z));
        atomicAdd(dst + 3, (r0.w + r1.w) + (r2.w + r3.w));
    }
}

extern "C" void kernel_launch(void* const* d_in, const int* in_sizes, int n_in,
                              void* d_out, int out_size)
{
    const float* states = (const float*)d_in[0];
    const float* key    = (const float*)d_in[1];
    const float* value  = (const float*)d_in[2];
    const float* alpha  = (const float*)d_in[3];
    const float* rho    = (const float*)d_in[4];
    const float* lam    = (const float*)d_in[5];
    const float* query  = (const float*)d_in[6];

    float* out_states = (float*)d_out;
    float* out_read   = (float*)d_out + STATES_ELEMS;

    // Zero the readout region (atomically accumulated). Memset nodes are
    // graph-capturable.
    cudaMemsetAsync(out_read, 0, READ_ELEMS * sizeof(float));

    dim3 block(64, 4);
    dim3 grid(N_MEM * BATCH * 4);
    mom_fused_kernel<<<grid, block>>>(states, key, value, alpha, rho, lam, query,
                                      out_states, out_read);
}

// round 4
// speedup vs baseline: 1.0858x; 1.0858x over previous
#include <cuda_runtime.h>
#include <cstddef>

#define N_MEM 8
#define BATCH 64
#define D_K 256
#define D_V 256
#define KCHUNK 128   // k-rows per CTA (D_K / 2)

// out layout: new_states [N_MEM, B, D_K, D_V] followed by readouts [N_MEM, B, D_V]
#define STATES_ELEMS ((size_t)N_MEM * BATCH * D_K * D_V)
#define READ_ELEMS   ((size_t)N_MEM * BATCH * D_V)

__global__ __launch_bounds__(256, 8)
void mom_fused_kernel(const float* __restrict__ states,
                      const float* __restrict__ key,
                      const float* __restrict__ value,
                      const float* __restrict__ alpha,
                      const float* __restrict__ rho,
                      const float* __restrict__ lam,
                      const float* __restrict__ query,
                      float* __restrict__ out_states,
                      float* __restrict__ out_read)
{
    // blockIdx.x = (n*BATCH + b) * 2 + kchunk
    const int blk = blockIdx.x;
    const int nb  = blk >> 1;        // slice index: n*BATCH + b
    const int kc  = blk & 1;         // which 128-row k chunk
    const int n   = nb / BATCH;
    const int b   = nb - n * BATCH;

    const int tx  = threadIdx.x;     // 0..63 : D_V in float4 units
    const int ty  = threadIdx.y;     // 0..3  : k-row partition within chunk
    const int tid = ty * 64 + tx;

    const float lam_s = lam[b * N_MEM + n];
    const float w     = rho[b * N_MEM + n] * alpha[b];

    __shared__ float skey[KCHUNK];
    __shared__ float sq[KCHUNK];
    if (tid < KCHUNK) {
        const int k = kc * KCHUNK + tid;
        skey[tid] = key[b * D_K + k] * w;  // pre-scale key by write strength
        sq[tid]   = query[b * D_K + k];
    }
    __syncthreads();

    const size_t base = (size_t)nb * D_K * D_V + (size_t)kc * KCHUNK * D_V;
    const float4* __restrict__ st  = (const float4*)(states + base);
    float4* __restrict__       ost = (float4*)(out_states + base);

    const float4 val4 = ((const float4*)(value + b * D_V))[tx];

    float4 acc = make_float4(0.f, 0.f, 0.f, 0.f);

    // 32 k-rows per thread, plain cached loads/stores, deep unroll for MLP
    #pragma unroll 8
    for (int kk = ty; kk < KCHUNK; kk += 4) {
        float4 s = st[kk * 64 + tx];
        const float kw = skey[kk];
        float4 ns;
        ns.x = lam_s * s.x + kw * val4.x;
        ns.y = lam_s * s.y + kw * val4.y;
        ns.z = lam_s * s.z + kw * val4.z;
        ns.w = lam_s * s.w + kw * val4.w;
        ost[kk * 64 + tx] = ns;
        const float q = sq[kk];
        acc.x += q * ns.x;
        acc.y += q * ns.y;
        acc.z += q * ns.z;
        acc.w += q * ns.w;
    }

    // Cross-ty reduction, then one float4-worth of atomics per lane
    __shared__ float4 red[4][64];
    red[ty][tx] = acc;
    __syncthreads();
    if (ty == 0) {
        float4 r0 = red[0][tx];
        float4 r1 = red[1][tx];
        float4 r2 = red[2][tx];
        float4 r3 = red[3][tx];
        float* dst = out_read + (size_t)nb * D_V + tx * 4;
        atomicAdd(dst + 0, (r0.x + r1.x) + (r2.x + r3.x));
        atomicAdd(dst + 1, (r0.y + r1.y) + (r2.y + r3.y));
        atomicAdd(dst + 2, (r0.z + r1.z) + (r2.z + r3.z));
        atomicAdd(dst + 3, (r0.w + r1.w) + (r2.w + r3.w));
    }
}

extern "C" void kernel_launch(void* const* d_in, const int* in_sizes, int n_in,
                              void* d_out, int out_size)
{
    const float* states = (const float*)d_in[0];
    const float* key    = (const float*)d_in[1];
    const float* value  = (const float*)d_in[2];
    const float* alpha  = (const float*)d_in[3];
    const float* rho    = (const float*)d_in[4];
    const float* lam    = (const float*)d_in[5];
    const float* query  = (const float*)d_in[6];

    float* out_states = (float*)d_out;
    float* out_read   = (float*)d_out + STATES_ELEMS;

    // Zero the readout region (atomically accumulated across the 2 k-chunk CTAs
    // per slice). Memset nodes are graph-capturable.
    cudaMemsetAsync(out_read, 0, READ_ELEMS * sizeof(float));

    dim3 block(64, 4);
    dim3 grid(N_MEM * BATCH * 2);
    mom_fused_kernel<<<grid, block>>>(states, key, value, alpha, rho, lam, query,
                                      out_states, out_read);
}

// round 5
// speedup vs baseline: 1.1293x; 1.0401x over previous
#include <cuda_runtime.h>
#include <cstddef>

#define N_MEM 8
#define BATCH 64
#define D_K 256
#define D_V 256
#define KCHUNK 128   // k-rows per CTA (D_K / 2)
#define RPT 8        // rows per thread per batch (MLP depth)

// out layout: new_states [N_MEM, B, D_K, D_V] followed by readouts [N_MEM, B, D_V]
#define STATES_ELEMS ((size_t)N_MEM * BATCH * D_K * D_V)
#define READ_ELEMS   ((size_t)N_MEM * BATCH * D_V)

__global__ __launch_bounds__(256, 4)
void mom_fused_kernel(const float* __restrict__ states,
                      const float* __restrict__ key,
                      const float* __restrict__ value,
                      const float* __restrict__ alpha,
                      const float* __restrict__ rho,
                      const float* __restrict__ lam,
                      const float* __restrict__ query,
                      float* __restrict__ out_states,
                      float* __restrict__ out_read)
{
    // blockIdx.x = (n*BATCH + b) * 2 + kchunk
    const int blk = blockIdx.x;
    const int nb  = blk >> 1;        // slice index: n*BATCH + b
    const int kc  = blk & 1;         // which 128-row k chunk
    const int n   = nb / BATCH;
    const int b   = nb - n * BATCH;

    const int tx  = threadIdx.x;     // 0..63 : D_V in float4 units
    const int ty  = threadIdx.y;     // 0..3  : k-row partition within chunk
    const int tid = ty * 64 + tx;

    const float lam_s = lam[b * N_MEM + n];
    const float w     = rho[b * N_MEM + n] * alpha[b];

    __shared__ float skey[KCHUNK];
    __shared__ float sq[KCHUNK];
    if (tid < KCHUNK) {
        const int k = kc * KCHUNK + tid;
        skey[tid] = key[b * D_K + k] * w;  // pre-scale key by write strength
        sq[tid]   = query[b * D_K + k];
    }
    __syncthreads();

    const size_t base = (size_t)nb * D_K * D_V + (size_t)kc * KCHUNK * D_V;
    const float4* __restrict__ st  = (const float4*)(states + base);
    float4* __restrict__       ost = (float4*)(out_states + base);

    const float4 val4 = ((const float4*)(value + b * D_V))[tx];

    float4 acc = make_float4(0.f, 0.f, 0.f, 0.f);

    // 32 k-rows per thread, processed in batches of RPT=8:
    // issue 8 independent LDG.128 back-to-back (MLP=8), then compute+store.
    for (int c = 0; c < KCHUNK; c += 4 * RPT) {
        float4 s[RPT];
        #pragma unroll
        for (int j = 0; j < RPT; j++) {
            const int kk = c + ty + j * 4;
            s[j] = st[kk * 64 + tx];
        }
        #pragma unroll
        for (int j = 0; j < RPT; j++) {
            const int kk = c + ty + j * 4;
            const float kw = skey[kk];
            float4 ns;
            ns.x = lam_s * s[j].x + kw * val4.x;
            ns.y = lam_s * s[j].y + kw * val4.y;
            ns.z = lam_s * s[j].z + kw * val4.z;
            ns.w = lam_s * s[j].w + kw * val4.w;
            ost[kk * 64 + tx] = ns;
            const float q = sq[kk];
            acc.x += q * ns.x;
            acc.y += q * ns.y;
            acc.z += q * ns.z;
            acc.w += q * ns.w;
        }
    }

    // Cross-ty reduction, then one float4-worth of atomics per lane
    __shared__ float4 red[4][64];
    red[ty][tx] = acc;
    __syncthreads();
    if (ty == 0) {
        float4 r0 = red[0][tx];
        float4 r1 = red[1][tx];
        float4 r2 = red[2][tx];
        float4 r3 = red[3][tx];
        float* dst = out_read + (size_t)nb * D_V + tx * 4;
        atomicAdd(dst + 0, (r0.x + r1.x) + (r2.x + r3.x));
        atomicAdd(dst + 1, (r0.y + r1.y) + (r2.y + r3.y));
        atomicAdd(dst + 2, (r0.z + r1.z) + (r2.z + r3.z));
        atomicAdd(dst + 3, (r0.w + r1.w) + (r2.w + r3.w));
    }
}

extern "C" void kernel_launch(void* const* d_in, const int* in_sizes, int n_in,
                              void* d_out, int out_size)
{
    const float* states = (const float*)d_in[0];
    const float* key    = (const float*)d_in[1];
    const float* value  = (const float*)d_in[2];
    const float* alpha  = (const float*)d_in[3];
    const float* rho    = (const float*)d_in[4];
    const float* lam    = (const float*)d_in[5];
    const float* query  = (const float*)d_in[6];

    float* out_states = (float*)d_out;
    float* out_read   = (float*)d_out + STATES_ELEMS;

    // Zero the readout region (atomically accumulated across the 2 k-chunk CTAs
    // per slice). Memset nodes are graph-capturable.
    cudaMemsetAsync(out_read, 0, READ_ELEMS * sizeof(float));

    dim3 block(64, 4);
    dim3 grid(N_MEM * BATCH * 2);
    mom_fused_kernel<<<grid, block>>>(states, key, value, alpha, rho, lam, query,
                                      out_states, out_read);
}

// round 6
// speedup vs baseline: 1.1501x; 1.0184x over previous
#include <cuda_runtime.h>
#include <cstddef>

#define N_MEM 8
#define BATCH 64
#define D_K 256
#define D_V 256
#define KCHUNK 128   // k-rows per CTA (D_K / 2)
#define RPT 8        // rows per thread per batch (MLP depth)
#define NBATCH (KCHUNK / (4 * RPT))   // 4 batches of 8 rows per thread

// out layout: new_states [N_MEM, B, D_K, D_V] followed by readouts [N_MEM, B, D_V]
#define STATES_ELEMS ((size_t)N_MEM * BATCH * D_K * D_V)
#define READ_ELEMS   ((size_t)N_MEM * BATCH * D_V)

__global__ __launch_bounds__(256, 2)
void mom_fused_kernel(const float* __restrict__ states,
                      const float* __restrict__ key,
                      const float* __restrict__ value,
                      const float* __restrict__ alpha,
                      const float* __restrict__ rho,
                      const float* __restrict__ lam,
                      const float* __restrict__ query,
                      float* __restrict__ out_states,
                      float* __restrict__ out_read)
{
    // blockIdx.x = (n*BATCH + b) * 2 + kchunk
    const int blk = blockIdx.x;
    const int nb  = blk >> 1;        // slice index: n*BATCH + b
    const int kc  = blk & 1;         // which 128-row k chunk
    const int n   = nb / BATCH;
    const int b   = nb - n * BATCH;

    const int tx  = threadIdx.x;     // 0..63 : D_V in float4 units
    const int ty  = threadIdx.y;     // 0..3  : k-row partition within chunk
    const int tid = ty * 64 + tx;

    const float lam_s = lam[b * N_MEM + n];
    const float w     = rho[b * N_MEM + n] * alpha[b];

    __shared__ float skey[KCHUNK];
    __shared__ float sq[KCHUNK];
    if (tid < KCHUNK) {
        const int k = kc * KCHUNK + tid;
        skey[tid] = key[b * D_K + k] * w;  // pre-scale key by write strength
        sq[tid]   = query[b * D_K + k];
    }
    __syncthreads();

    const size_t base = (size_t)nb * D_K * D_V + (size_t)kc * KCHUNK * D_V;
    const float4* __restrict__ st  = (const float4*)(states + base);
    float4* __restrict__       ost = (float4*)(out_states + base);

    const float4 val4 = ((const float4*)(value + b * D_V))[tx];

    float4 acc = make_float4(0.f, 0.f, 0.f, 0.f);

    // Software-pipelined double buffer: loads for batch j+1 are issued before
    // the compute+store of batch j, so the LSU always has ~8 LDG.128 in flight.
    float4 s[2][RPT];

    #pragma unroll
    for (int j = 0; j < RPT; j++)
        s[0][j] = st[(ty + j * 4) * 64 + tx];

    #pragma unroll
    for (int cb = 0; cb < NBATCH; cb++) {
        const int cur = cb & 1;
        const int nxt = cur ^ 1;
        const int cbase = cb * 4 * RPT;

        if (cb + 1 < NBATCH) {
            const int pbase = (cb + 1) * 4 * RPT;
            #pragma unroll
            for (int j = 0; j < RPT; j++)
                s[nxt][j] = st[(pbase + ty + j * 4) * 64 + tx];
        }

        #pragma unroll
        for (int j = 0; j < RPT; j++) {
            const int kk = cbase + ty + j * 4;
            const float kw = skey[kk];
            float4 ns;
            ns.x = lam_s * s[cur][j].x + kw * val4.x;
            ns.y = lam_s * s[cur][j].y + kw * val4.y;
            ns.z = lam_s * s[cur][j].z + kw * val4.z;
            ns.w = lam_s * s[cur][j].w + kw * val4.w;
            ost[kk * 64 + tx] = ns;
            const float q = sq[kk];
            acc.x += q * ns.x;
            acc.y += q * ns.y;
            acc.z += q * ns.z;
            acc.w += q * ns.w;
        }
    }

    // Cross-ty reduction, then one float4-worth of atomics per lane
    __shared__ float4 red[4][64];
    red[ty][tx] = acc;
    __syncthreads();
    if (ty == 0) {
        float4 r0 = red[0][tx];
        float4 r1 = red[1][tx];
        float4 r2 = red[2][tx];
        float4 r3 = red[3][tx];
        float* dst = out_read + (size_t)nb * D_V + tx * 4;
        atomicAdd(dst + 0, (r0.x + r1.x) + (r2.x + r3.x));
        atomicAdd(dst + 1, (r0.y + r1.y) + (r2.y + r3.y));
        atomicAdd(dst + 2, (r0.z + r1.z) + (r2.z + r3.z));
        atomicAdd(dst + 3, (r0.w + r1.w) + (r2.w + r3.w));
    }
}

extern "C" void kernel_launch(void* const* d_in, const int* in_sizes, int n_in,
                              void* d_out, int out_size)
{
    const float* states = (const float*)d_in[0];
    const float* key    = (const float*)d_in[1];
    const float* value  = (const float*)d_in[2];
    const float* alpha  = (const float*)d_in[3];
    const float* rho    = (const float*)d_in[4];
    const float* lam    = (const float*)d_in[5];
    const float* query  = (const float*)d_in[6];

    float* out_states = (float*)d_out;
    float* out_read   = (float*)d_out + STATES_ELEMS;

    // Zero the readout region (atomically accumulated across the 2 k-chunk CTAs
    // per slice). Memset nodes are graph-capturable.
    cudaMemsetAsync(out_read, 0, READ_ELEMS * sizeof(float));

    dim3 block(64, 4);
    dim3 grid(N_MEM * BATCH * 2);
    mom_fused_kernel<<<grid, block>>>(states, key, value, alpha, rho, lam, query,
                                      out_states, out_read);
}